// round 15
// baseline (speedup 1.0000x reference)
#include <cuda_runtime.h>
#include <cuda_bf16.h>
#include <math.h>
#include <stdint.h>

#define NROWS 4096
#define DDIM  512
#define BM 128
#define BN 128
#define NB (NROWS / BM)         // 32 tiles per dim
#define NTRI (NB * (NB + 1) / 2)   // 528 upper-triangle tiles
#define NSUB 32                 // 32 k16 sub-chunks (32 B per row each)
#define ROWB 32                 // smem row stride (XOR swizzle, no pad)
#define TILEB (128 * ROWB)      // 4096 B per operand tile
#define STAGEB (4 * TILEB)      // Ahi, Alo, Bhi, Blo = 16384 B

// ---- scratch (no cudaMalloc allowed) ----
__device__ __align__(16) __nv_bfloat16 g_hi[NROWS * DDIM];
__device__ __align__(16) __nv_bfloat16 g_lo[NROWS * DDIM];
__device__ float g_ps[NROWS];
__device__ float g_ns[NROWS];
__device__ float g_pc[NROWS];
__device__ float g_nc[NROWS];

__device__ __forceinline__ uint32_t smem_u32(const void* p) {
    return (uint32_t)__cvta_generic_to_shared(p);
}

__device__ __forceinline__ float softplus_f(float x) {
    return fmaxf(x, 0.f) + __logf(1.f + __expf(-fabsf(x)));
}

#define LDSM4(R, ADDR)                                                         \
    asm volatile("ldmatrix.sync.aligned.m8n8.x4.shared.b16 {%0,%1,%2,%3}, [%4];" \
                 : "=r"((R)[0]), "=r"((R)[1]), "=r"((R)[2]), "=r"((R)[3])      \
                 : "r"(ADDR))

#define MMA16816(C, A0, A1, A2, A3, B0, B1)                                    \
    asm volatile("mma.sync.aligned.m16n8k16.row.col.f32.bf16.bf16.f32 "        \
                 "{%0,%1,%2,%3}, {%4,%5,%6,%7}, {%8,%9}, {%0,%1,%2,%3};"       \
                 : "+f"((C)[0]), "+f"((C)[1]), "+f"((C)[2]), "+f"((C)[3])      \
                 : "r"(A0), "r"(A1), "r"(A2), "r"(A3), "r"(B0), "r"(B1))

// ============================================================================
// prep: fp32 -> bf16 hi/lo split; zeros per-row stat arrays.
// 1024 threads, 8 elements per thread.
// ============================================================================
__global__ void __launch_bounds__(1024) prep_kernel(const float* __restrict__ X) {
    int i = blockIdx.x * blockDim.x + threadIdx.x;   // 0 .. 262143
    int base = i * 8;
    if (base < NROWS * DDIM) {
#pragma unroll
        for (int h = 0; h < 2; h++) {
            float4 v = *(const float4*)&X[base + h * 4];
            float f[4] = {v.x, v.y, v.z, v.w};
#pragma unroll
            for (int k = 0; k < 4; k++) {
                __nv_bfloat16 hv = __float2bfloat16(f[k]);
                g_hi[base + h * 4 + k] = hv;
                g_lo[base + h * 4 + k] = __float2bfloat16(f[k] - __bfloat162float(hv));
            }
        }
    }
    if (i < NROWS) { g_ps[i] = 0.f; g_ns[i] = 0.f; g_pc[i] = 0.f; g_nc[i] = 0.f; }
}

// ============================================================================
// main: bf16 hi/lo-split mma.sync GEMM + fused softplus stats.
// Triangular grid (528 CTAs); static smem; R11/R14-proven reg-prefetch
// schedule; diagonal tiles alias B onto A; rolled mainloop (I$-resident).
// ============================================================================
__global__ void __launch_bounds__(256, 2)
sim_loss_mma(const long long* __restrict__ tgt) {
    // triangular decode: blockIdx.x -> (bi, bj), bi <= bj
    const int t = (int)blockIdx.x;
    int bi = (int)((2.f * NB + 1.f - sqrtf((2.f * NB + 1.f) * (2.f * NB + 1.f)
                                           - 8.f * (float)t)) * 0.5f);
    while (bi > 0 && bi * (2 * NB + 1 - bi) / 2 > t) bi--;
    while ((bi + 1) * (2 * NB + 1 - (bi + 1)) / 2 <= t) bi++;
    const int bj = bi + (t - bi * (2 * NB + 1 - bi) / 2);
    const bool offdiag = (bi != bj);

    __shared__ __align__(16) char s_tiles[2 * STAGEB];   // 32 KB, 2 stages
    __shared__ int   s_ti[128], s_tj[128];
    __shared__ float s_rps[128], s_rns[128], s_rpc[128], s_rnc[128];
    __shared__ float s_cps[128], s_cns[128], s_cpc[128], s_cnc[128];

    const int tid  = threadIdx.x;
    const int wid  = tid >> 5;
    const int lane = tid & 31;
    const int warp_m = wid & 3;    // 4 warps along M (32 rows each)
    const int warp_n = wid >> 2;   // 2 warps along N (64 cols each)

    if (tid < 128) {
        s_ti[tid] = (int)tgt[bi * BM + tid];
        s_rps[tid] = 0.f; s_rns[tid] = 0.f; s_rpc[tid] = 0.f; s_rnc[tid] = 0.f;
    } else {
        s_tj[tid - 128] = (int)tgt[bj * BN + tid - 128];
        s_cps[tid - 128] = 0.f; s_cns[tid - 128] = 0.f;
        s_cpc[tid - 128] = 0.f; s_cnc[tid - 128] = 0.f;
    }

    const char* src0 = (const char*)(g_hi + (size_t)bi * BM * DDIM);   // Ahi
    const char* src1 = (const char*)(g_lo + (size_t)bi * BM * DDIM);   // Alo
    const char* src2 = (const char*)(g_hi + (size_t)bj * BN * DDIM);   // Bhi
    const char* src3 = (const char*)(g_lo + (size_t)bj * BN * DDIM);   // Blo

    // per-thread fill coords: 128 rows x 2 sixteen-byte quads per tile
    const int frow = tid >> 1;
    const int fqb  = (tid & 1) * 16;
    const uint32_t fso = ((uint32_t)(frow * ROWB + fqb)) ^ (((uint32_t)frow & 4u) << 2);
    char* fdst = s_tiles + fso;
    const char* fsrc_base0 = src0 + frow * 1024 + fqb;
    const char* fsrc_base1 = src1 + frow * 1024 + fqb;
    const char* fsrc_base2 = src2 + frow * 1024 + fqb;
    const char* fsrc_base3 = src3 + frow * 1024 + fqb;

    const uint32_t stile = smem_u32(s_tiles);
    const uint32_t a_off0 = (((uint32_t)((warp_m * 32 + (lane & 15)) * ROWB + (lane >> 4) * 16))
                             ^ (((uint32_t)lane & 4u) << 2));
    const int browb = warp_n * 64 + ((lane >> 4) << 3) + (lane & 7);
    const uint32_t b_off0 = (((uint32_t)(browb * ROWB + ((lane >> 3) & 1) * 16))
                             ^ (((uint32_t)lane & 4u) << 2));
    // diagonal tiles: B data == A data; read B fragments from the A tiles
    const uint32_t b_tile_h = offdiag ? 2u * TILEB : 0u;
    const uint32_t b_tile_l = offdiag ? 3u * TILEB : 1u * TILEB;

    float acc[2][8][4];
#pragma unroll
    for (int mi = 0; mi < 2; mi++)
#pragma unroll
        for (int ni = 0; ni < 8; ni++)
#pragma unroll
            for (int x = 0; x < 4; x++) acc[mi][ni][x] = 0.f;

    // ---- prologue: fetch sub 0 and store into stage 0 ----
    float4 pf0 = *(const float4*)(fsrc_base0);
    float4 pf1 = *(const float4*)(fsrc_base1);
    float4 pf2 = make_float4(0.f, 0.f, 0.f, 0.f);
    float4 pf3 = make_float4(0.f, 0.f, 0.f, 0.f);
    *(float4*)(fdst + 0 * TILEB) = pf0;
    *(float4*)(fdst + 1 * TILEB) = pf1;
    if (offdiag) {
        pf2 = *(const float4*)(fsrc_base2);
        pf3 = *(const float4*)(fsrc_base3);
        *(float4*)(fdst + 2 * TILEB) = pf2;
        *(float4*)(fdst + 3 * TILEB) = pf3;
    }

#pragma unroll 1
    for (int sub = 0; sub < NSUB; sub++) {
        __syncthreads();   // stage sub&1 fully written; stage^1 readers done

        const bool more = (sub + 1 < NSUB);
        if (more) {        // issue global loads early; consumed at bottom of loop
            const int go = (sub + 1) * 32;
            pf0 = *(const float4*)(fsrc_base0 + go);
            pf1 = *(const float4*)(fsrc_base1 + go);
            if (offdiag) {
                pf2 = *(const float4*)(fsrc_base2 + go);
                pf3 = *(const float4*)(fsrc_base3 + go);
            }
        }

        const uint32_t st = stile + (uint32_t)(sub & 1) * STAGEB;
        uint32_t ah[2][4], al[2][4];
#pragma unroll
        for (int mi = 0; mi < 2; mi++) {
            const uint32_t ao = a_off0 + (uint32_t)(mi * 16 * ROWB);
            LDSM4(ah[mi], st + 0 * TILEB + ao);
            LDSM4(al[mi], st + 1 * TILEB + ao);
        }
#pragma unroll
        for (int ng = 0; ng < 4; ng++) {
            uint32_t bh[4], bl[4];
            const uint32_t bo = b_off0 + (uint32_t)(ng * 16 * ROWB);
            LDSM4(bh, st + b_tile_h + bo);
            LDSM4(bl, st + b_tile_l + bo);
#pragma unroll
            for (int mi = 0; mi < 2; mi++) {
                float* c0 = acc[mi][ng * 2 + 0];
                float* c1 = acc[mi][ng * 2 + 1];
                MMA16816(c0, ah[mi][0], ah[mi][1], ah[mi][2], ah[mi][3], bh[0], bh[1]);
                MMA16816(c1, ah[mi][0], ah[mi][1], ah[mi][2], ah[mi][3], bh[2], bh[3]);
                MMA16816(c0, ah[mi][0], ah[mi][1], ah[mi][2], ah[mi][3], bl[0], bl[1]);
                MMA16816(c1, ah[mi][0], ah[mi][1], ah[mi][2], ah[mi][3], bl[2], bl[3]);
                MMA16816(c0, al[mi][0], al[mi][1], al[mi][2], al[mi][3], bh[0], bh[1]);
                MMA16816(c1, al[mi][0], al[mi][1], al[mi][2], al[mi][3], bh[2], bh[3]);
            }
        }

        if (more) {        // store prefetched sub+1 into the other stage
            char* d = fdst + (((sub + 1) & 1) ? STAGEB : 0);
            *(float4*)(d + 0 * TILEB) = pf0;
            *(float4*)(d + 1 * TILEB) = pf1;
            if (offdiag) {
                *(float4*)(d + 2 * TILEB) = pf2;
                *(float4*)(d + 3 * TILEB) = pf3;
            }
        }
    }

    // ================= fused epilogue (R7/R9/R11/R14-proven) =================
    const int laneq = lane >> 2, lane4 = lane & 3;
    int tr[4];
#pragma unroll
    for (int ri = 0; ri < 4; ri++)
        tr[ri] = s_ti[warp_m * 32 + (ri >> 1) * 16 + laneq + (ri & 1) * 8];

    float rps[4] = {0,0,0,0}, rns[4] = {0,0,0,0}, rpc[4] = {0,0,0,0}, rnc[4] = {0,0,0,0};

#pragma unroll
    for (int ni = 0; ni < 8; ni++) {
#pragma unroll
        for (int cb = 0; cb < 2; cb++) {
            const int col = warp_n * 64 + ni * 8 + lane4 * 2 + cb;
            const int tc = s_tj[col];
            float cps = 0.f, cns = 0.f, cpc = 0.f, cnc = 0.f;
#pragma unroll
            for (int mi = 0; mi < 2; mi++)
#pragma unroll
                for (int half = 0; half < 2; half++) {
                    const float sv = acc[mi][ni][half * 2 + cb];
                    const int ri = mi * 2 + half;
                    if (tr[ri] == tc) {
                        if (sv < 1.f) {
                            float p = softplus_f(-2.f * (sv - 0.5f));
                            rps[ri] += p; cps += p;
                            rpc[ri] += 1.f; cpc += 1.f;
                        }
                    } else {
                        float nterm = softplus_f(25.f * (sv - 0.5f));
                        rns[ri] += nterm; cns += nterm;
                        rnc[ri] += 1.f; cnc += 1.f;
                    }
                }
            if (offdiag) {
#pragma unroll
                for (int o = 4; o < 32; o <<= 1) {
                    cps += __shfl_xor_sync(0xffffffffu, cps, o);
                    cns += __shfl_xor_sync(0xffffffffu, cns, o);
                    cpc += __shfl_xor_sync(0xffffffffu, cpc, o);
                    cnc += __shfl_xor_sync(0xffffffffu, cnc, o);
                }
                if (laneq == 0) {
                    atomicAdd(&s_cns[col], cns);
                    atomicAdd(&s_cnc[col], cnc);
                    if (cpc != 0.f) {
                        atomicAdd(&s_cps[col], cps);
                        atomicAdd(&s_cpc[col], cpc);
                    }
                }
            }
        }
    }
#pragma unroll
    for (int ri = 0; ri < 4; ri++) {
        float p = rps[ri], a = rns[ri], q = rpc[ri], b = rnc[ri];
        p += __shfl_xor_sync(0xffffffffu, p, 1); p += __shfl_xor_sync(0xffffffffu, p, 2);
        a += __shfl_xor_sync(0xffffffffu, a, 1); a += __shfl_xor_sync(0xffffffffu, a, 2);
        q += __shfl_xor_sync(0xffffffffu, q, 1); q += __shfl_xor_sync(0xffffffffu, q, 2);
        b += __shfl_xor_sync(0xffffffffu, b, 1); b += __shfl_xor_sync(0xffffffffu, b, 2);
        if (lane4 == 0) {
            const int r = warp_m * 32 + (ri >> 1) * 16 + laneq + (ri & 1) * 8;
            atomicAdd(&s_rns[r], a);
            atomicAdd(&s_rnc[r], b);
            if (q != 0.f) {
                atomicAdd(&s_rps[r], p);
                atomicAdd(&s_rpc[r], q);
            }
        }
    }
    __syncthreads();

    if (tid < 128) {
        const int r = bi * BM + tid;
        atomicAdd(&g_ns[r], s_rns[tid]);
        atomicAdd(&g_nc[r], s_rnc[tid]);
        if (s_rpc[tid] != 0.f) {
            atomicAdd(&g_ps[r], s_rps[tid]);
            atomicAdd(&g_pc[r], s_rpc[tid]);
        }
    } else if (offdiag) {
        const int t2 = tid - 128;
        const int cidx = bj * BN + t2;
        atomicAdd(&g_ns[cidx], s_cns[t2]);
        atomicAdd(&g_nc[cidx], s_cnc[t2]);
        if (s_cpc[t2] != 0.f) {
            atomicAdd(&g_ps[cidx], s_cps[t2]);
            atomicAdd(&g_pc[cidx], s_cpc[t2]);
        }
    }
}

// ============================================================================
// finalize: per-row means; global mean (1024 threads)
// ============================================================================
__global__ void __launch_bounds__(1024) finalize_kernel(float* out) {
    __shared__ float red[1024];
    float local = 0.f;
    for (int r = threadIdx.x; r < NROWS; r += 1024) {
        float pc = g_pc[r], nc = g_nc[r];
        float pm = (pc > 0.f) ? g_ps[r] / fmaxf(pc, 1.f) : 0.f;
        float nm = (nc > 0.f) ? g_ns[r] / fmaxf(nc, 1.f) : 0.f;
        local += pm + nm;
    }
    red[threadIdx.x] = local;
    __syncthreads();
    for (int off = 512; off > 0; off >>= 1) {
        if (threadIdx.x < off) red[threadIdx.x] += red[threadIdx.x + off];
        __syncthreads();
    }
    if (threadIdx.x == 0) out[0] = red[0] / (float)NROWS;
}

extern "C" void kernel_launch(void* const* d_in, const int* in_sizes, int n_in,
                              void* d_out, int out_size) {
    const float* X = (const float*)d_in[0];
    const long long* tgt = (const long long*)d_in[1];
    float* out = (float*)d_out;

    prep_kernel<<<NROWS * DDIM / (8 * 1024), 1024>>>(X);
    sim_loss_mma<<<NTRI, 256>>>(tgt);
    finalize_kernel<<<1, 1024>>>(out);
}